// round 1
// baseline (speedup 1.0000x reference)
#include <cuda_runtime.h>
#include <cuda_bf16.h>
#include <cstdint>

// Problem constants
#define NN   16
#define CC   64      // Cin == Cout == 64
#define HH   128
#define NT   32      // tiles per side
#define BB   (NN * NT * NT)   // 16384 tile positions
#define AB   36

// Scratch (device globals; no runtime allocation allowed)
__device__ float g_V[(size_t)AB * CC * BB];   // V[ab][i][B]
__device__ float g_M[(size_t)AB * CC * BB];   // M[ab][o][B]
__device__ float g_Wt[(size_t)AB * CC * CC];  // W[ab][i][o]

// ---------------------------------------------------------------------------
// Kernel 0: repack weights (Cout, Cin, 6, 6) -> Wt[ab][i][o]
// ---------------------------------------------------------------------------
__global__ __launch_bounds__(256) void wino_wt(const float* __restrict__ w) {
    int idx = blockIdx.x * 256 + threadIdx.x;   // 0 .. 36*64*64-1
    if (idx >= AB * CC * CC) return;
    int o  = idx & 63;
    int i  = (idx >> 6) & 63;
    int ab = idx >> 12;
    g_Wt[idx] = w[(o * CC + i) * AB + ab];
}

// ---------------------------------------------------------------------------
// Kernel 1: input transform. V[a][b] = BT * d * BT^T per (channel, tile)
// grid = N*NT blocks (n,p), block = (32 q-lanes, 8), loop over channels
// ---------------------------------------------------------------------------
__global__ __launch_bounds__(256) void wino_in(const float* __restrict__ x) {
    const int q  = threadIdx.x;          // 0..31 (tile col) -> coalesced stores
    const int iy = threadIdx.y;          // 0..7
    const int blk = blockIdx.x;          // n*32 + p
    const int n = blk >> 5;
    const int p = blk & 31;
    const int Bidx = (n * NT + p) * NT + q;

    const int r0 = 4 * p - 1;            // padded origin (pad=1)
    const int c0 = 4 * q - 1;

    for (int i = iy; i < CC; i += 8) {
        const float* xp = x + ((size_t)(n * CC + i)) * (HH * HH);

        float d[6][6];
#pragma unroll
        for (int r = 0; r < 6; r++) {
            int gr = r0 + r;
            bool rok = ((unsigned)gr < (unsigned)HH);
#pragma unroll
            for (int c = 0; c < 6; c++) {
                int gc = c0 + c;
                d[r][c] = (rok && ((unsigned)gc < (unsigned)HH))
                              ? xp[gr * HH + gc] : 0.f;
            }
        }

        // rows: t[a][c] = BT_a . d[:,c]
        float t[6][6];
#pragma unroll
        for (int c = 0; c < 6; c++) {
            float d0 = d[0][c], d1 = d[1][c], d2 = d[2][c];
            float d3 = d[3][c], d4 = d[4][c], d5 = d[5][c];
            t[0][c] =  4.f * d0 - 5.f * d2 + d4;
            t[1][c] = -4.f * d1 - 4.f * d2 + d3 + d4;
            t[2][c] =  4.f * d1 - 4.f * d2 - d3 + d4;
            t[3][c] = -2.f * d1 -       d2 + 2.f * d3 + d4;
            t[4][c] =  2.f * d1 -       d2 - 2.f * d3 + d4;
            t[5][c] =  4.f * d1 - 5.f * d3 + d5;
        }

        // cols: V[a][b] = BT_b . t[a][:]
        const size_t outBase = (size_t)i * BB + Bidx;
#pragma unroll
        for (int a = 0; a < 6; a++) {
            float d0 = t[a][0], d1 = t[a][1], d2 = t[a][2];
            float d3 = t[a][3], d4 = t[a][4], d5 = t[a][5];
            float v0 =  4.f * d0 - 5.f * d2 + d4;
            float v1 = -4.f * d1 - 4.f * d2 + d3 + d4;
            float v2 =  4.f * d1 - 4.f * d2 - d3 + d4;
            float v3 = -2.f * d1 -       d2 + 2.f * d3 + d4;
            float v4 =  2.f * d1 -       d2 - 2.f * d3 + d4;
            float v5 =  4.f * d1 - 5.f * d3 + d5;
            g_V[(size_t)(a * 6 + 0) * CC * BB + outBase] = v0;
            g_V[(size_t)(a * 6 + 1) * CC * BB + outBase] = v1;
            g_V[(size_t)(a * 6 + 2) * CC * BB + outBase] = v2;
            g_V[(size_t)(a * 6 + 3) * CC * BB + outBase] = v3;
            g_V[(size_t)(a * 6 + 4) * CC * BB + outBase] = v4;
            g_V[(size_t)(a * 6 + 5) * CC * BB + outBase] = v5;
        }
    }
}

// ---------------------------------------------------------------------------
// Kernel 2: 36 x GEMM  M[ab] (64 x 16384) = W[ab] (64x64) * V[ab] (64x16384)
// block tile: 64 (all o) x 128 tiles, K=64. 256 threads, 4x8 reg tile.
// ---------------------------------------------------------------------------
__global__ __launch_bounds__(256) void wino_gemm() {
    const int ab = blockIdx.y;
    const int b0 = blockIdx.x * 128;

    __shared__ float Ws[64][64];    // [i][o]
    __shared__ float Vs[64][128];   // [i][t]

    const int tid = threadIdx.x;

    // load weights for this ab (coalesced float4 from repacked g_Wt)
    {
        const float4* src = reinterpret_cast<const float4*>(g_Wt + (size_t)ab * CC * CC);
        float4* dst = reinterpret_cast<float4*>(&Ws[0][0]);
#pragma unroll
        for (int idx = tid; idx < 1024; idx += 256) dst[idx] = src[idx];
    }
    // load V slab (coalesced float4)
    {
#pragma unroll
        for (int idx = tid; idx < 2048; idx += 256) {
            int i  = idx >> 5;         // 32 float4 per row
            int t4 = idx & 31;
            *reinterpret_cast<float4*>(&Vs[i][t4 * 4]) =
                *reinterpret_cast<const float4*>(g_V + ((size_t)ab * CC + i) * BB + b0 + t4 * 4);
        }
    }
    __syncthreads();

    const int tx = tid & 15;   // t-group (8 tiles)
    const int ty = tid >> 4;   // o-group (4 outs)

    float acc[4][8];
#pragma unroll
    for (int a = 0; a < 4; a++)
#pragma unroll
        for (int b = 0; b < 8; b++) acc[a][b] = 0.f;

#pragma unroll 16
    for (int k = 0; k < 64; k++) {
        float4 a4 = *reinterpret_cast<const float4*>(&Ws[k][ty * 4]);
        float4 bv0 = *reinterpret_cast<const float4*>(&Vs[k][tx * 8]);
        float4 bv1 = *reinterpret_cast<const float4*>(&Vs[k][tx * 8 + 4]);
        float av[4] = {a4.x, a4.y, a4.z, a4.w};
        float bvv[8] = {bv0.x, bv0.y, bv0.z, bv0.w, bv1.x, bv1.y, bv1.z, bv1.w};
#pragma unroll
        for (int a = 0; a < 4; a++)
#pragma unroll
            for (int b = 0; b < 8; b++) acc[a][b] += av[a] * bvv[b];
    }

#pragma unroll
    for (int a = 0; a < 4; a++) {
        int o = ty * 4 + a;
        float* mp = g_M + ((size_t)ab * CC + o) * BB + b0 + tx * 8;
        float4 r0 = make_float4(acc[a][0], acc[a][1], acc[a][2], acc[a][3]);
        float4 r1 = make_float4(acc[a][4], acc[a][5], acc[a][6], acc[a][7]);
        *reinterpret_cast<float4*>(mp)     = r0;
        *reinterpret_cast<float4*>(mp + 4) = r1;
    }
}

// ---------------------------------------------------------------------------
// Kernel 3: output transform Y = AT * M * AT^T + bias, write to y
// grid = (BB/256, 64 o), block = 256 (one tile position per thread)
// ---------------------------------------------------------------------------
__global__ __launch_bounds__(256) void wino_out(float* __restrict__ y,
                                                const float* __restrict__ bias) {
    const int o = blockIdx.y;
    const int Bidx = blockIdx.x * 256 + threadIdx.x;

    float m[36];
#pragma unroll
    for (int ab = 0; ab < 36; ab++)
        m[ab] = g_M[((size_t)ab * CC + o) * BB + Bidx];

    // rows: t[x][b] = AT_x . m[:,b]
    float t[4][6];
#pragma unroll
    for (int b = 0; b < 6; b++) {
        float m0 = m[b], m1 = m[6 + b], m2 = m[12 + b];
        float m3 = m[18 + b], m4 = m[24 + b], m5 = m[30 + b];
        t[0][b] = m0 + m1 + m2 + m3 + m4;
        t[1][b] = m1 - m2 + 2.f * m3 - 2.f * m4;
        t[2][b] = m1 + m2 + 4.f * m3 + 4.f * m4;
        t[3][b] = m1 - m2 + 8.f * m3 - 8.f * m4 + m5;
    }

    const float bv = bias[o];
    const int n = Bidx >> 10;
    const int rem = Bidx & 1023;
    const int p = rem >> 5;
    const int q = rem & 31;
    float* yp = y + (((size_t)(n * CC + o)) * HH + 4 * p) * HH + 4 * q;

#pragma unroll
    for (int x = 0; x < 4; x++) {
        float m0 = t[x][0], m1 = t[x][1], m2 = t[x][2];
        float m3 = t[x][3], m4 = t[x][4], m5 = t[x][5];
        float4 r;
        r.x = m0 + m1 + m2 + m3 + m4 + bv;
        r.y = m1 - m2 + 2.f * m3 - 2.f * m4 + bv;
        r.z = m1 + m2 + 4.f * m3 + 4.f * m4 + bv;
        r.w = m1 - m2 + 8.f * m3 - 8.f * m4 + m5 + bv;
        *reinterpret_cast<float4*>(yp + x * HH) = r;
    }
}

// ---------------------------------------------------------------------------
extern "C" void kernel_launch(void* const* d_in, const int* in_sizes, int n_in,
                              void* d_out, int out_size) {
    const float* x    = (const float*)d_in[0];
    const float* w    = (const float*)d_in[1];
    const float* bias = (const float*)d_in[2];
    float* y = (float*)d_out;

    wino_wt<<<(AB * CC * CC + 255) / 256, 256>>>(w);
    wino_in<<<NN * NT, dim3(32, 8)>>>(x);
    wino_gemm<<<dim3(BB / 128, AB), 256>>>();
    wino_out<<<dim3(BB / 256, CC), 256>>>(y, bias);
}

// round 2
// speedup vs baseline: 1.7300x; 1.7300x over previous
#include <cuda_runtime.h>
#include <cuda_bf16.h>
#include <cstdint>

// Problem constants
#define NN   16
#define CC   64      // Cin == Cout == 64
#define HH   128
#define NT   32      // tiles per side
#define BB   (NN * NT * NT)   // 16384 tile positions
#define AB   36

// Scratch (device globals; no runtime allocation allowed)
__device__ float g_V[(size_t)AB * CC * BB];   // V[ab][i][B]   (tf32-rounded)
__device__ float g_M[(size_t)AB * CC * BB];   // M[ab][o][B]
__device__ float g_Wt[(size_t)AB * CC * CC];  // W[ab][i][o]   (tf32-rounded)

__device__ __forceinline__ float to_tf32(float x) {
    uint32_t u;
    asm("cvt.rna.tf32.f32 %0, %1;" : "=r"(u) : "f"(x));
    return __uint_as_float(u);
}

// ---------------------------------------------------------------------------
// Kernel 0: repack weights (Cout, Cin, 6, 6) -> Wt[ab][i][o], tf32-rounded
// ---------------------------------------------------------------------------
__global__ __launch_bounds__(256) void wino_wt(const float* __restrict__ w) {
    int idx = blockIdx.x * 256 + threadIdx.x;   // 0 .. 36*64*64-1
    if (idx >= AB * CC * CC) return;
    int o  = idx & 63;
    int i  = (idx >> 6) & 63;
    int ab = idx >> 12;
    g_Wt[idx] = to_tf32(w[(o * CC + i) * AB + ab]);
}

// ---------------------------------------------------------------------------
// Kernel 1: input transform. V[a][b] = BT * d * BT^T per (channel, tile)
// grid = N*NT blocks (n,p), block = (32 q-lanes, 8), loop over channels
// ---------------------------------------------------------------------------
__global__ __launch_bounds__(256) void wino_in(const float* __restrict__ x) {
    const int q  = threadIdx.x;          // 0..31 (tile col) -> coalesced stores
    const int iy = threadIdx.y;          // 0..7
    const int blk = blockIdx.x;          // n*32 + p
    const int n = blk >> 5;
    const int p = blk & 31;
    const int Bidx = (n * NT + p) * NT + q;

    const int r0 = 4 * p - 1;            // padded origin (pad=1)
    const int c0 = 4 * q - 1;

    for (int i = iy; i < CC; i += 8) {
        const float* xp = x + ((size_t)(n * CC + i)) * (HH * HH);

        float d[6][6];
#pragma unroll
        for (int r = 0; r < 6; r++) {
            int gr = r0 + r;
            bool rok = ((unsigned)gr < (unsigned)HH);
#pragma unroll
            for (int c = 0; c < 6; c++) {
                int gc = c0 + c;
                d[r][c] = (rok && ((unsigned)gc < (unsigned)HH))
                              ? xp[gr * HH + gc] : 0.f;
            }
        }

        // rows: t[a][c] = BT_a . d[:,c]
        float t[6][6];
#pragma unroll
        for (int c = 0; c < 6; c++) {
            float d0 = d[0][c], d1 = d[1][c], d2 = d[2][c];
            float d3 = d[3][c], d4 = d[4][c], d5 = d[5][c];
            t[0][c] =  4.f * d0 - 5.f * d2 + d4;
            t[1][c] = -4.f * d1 - 4.f * d2 + d3 + d4;
            t[2][c] =  4.f * d1 - 4.f * d2 - d3 + d4;
            t[3][c] = -2.f * d1 -       d2 + 2.f * d3 + d4;
            t[4][c] =  2.f * d1 -       d2 - 2.f * d3 + d4;
            t[5][c] =  4.f * d1 - 5.f * d3 + d5;
        }

        // cols: V[a][b] = BT_b . t[a][:]  (tf32-rounded at store)
        const size_t outBase = (size_t)i * BB + Bidx;
#pragma unroll
        for (int a = 0; a < 6; a++) {
            float d0 = t[a][0], d1 = t[a][1], d2 = t[a][2];
            float d3 = t[a][3], d4 = t[a][4], d5 = t[a][5];
            float v0 =  4.f * d0 - 5.f * d2 + d4;
            float v1 = -4.f * d1 - 4.f * d2 + d3 + d4;
            float v2 =  4.f * d1 - 4.f * d2 - d3 + d4;
            float v3 = -2.f * d1 -       d2 + 2.f * d3 + d4;
            float v4 =  2.f * d1 -       d2 - 2.f * d3 + d4;
            float v5 =  4.f * d1 - 5.f * d3 + d5;
            g_V[(size_t)(a * 6 + 0) * CC * BB + outBase] = to_tf32(v0);
            g_V[(size_t)(a * 6 + 1) * CC * BB + outBase] = to_tf32(v1);
            g_V[(size_t)(a * 6 + 2) * CC * BB + outBase] = to_tf32(v2);
            g_V[(size_t)(a * 6 + 3) * CC * BB + outBase] = to_tf32(v3);
            g_V[(size_t)(a * 6 + 4) * CC * BB + outBase] = to_tf32(v4);
            g_V[(size_t)(a * 6 + 5) * CC * BB + outBase] = to_tf32(v5);
        }
    }
}

// ---------------------------------------------------------------------------
// Kernel 2: 36 x GEMM  M[ab] (64 x 16384) = W[ab]^T (64x64) * V[ab] (64x16384)
// Tensor cores: mma.sync.m16n8k8 tf32. Block tile 64(o) x 128(t), K=64.
// 8 warps: 4 m-groups x 2 n-groups; warp tile 16 x 64.
// Smem XOR swizzle (col ^= (row&3)<<3) -> conflict-free fragment loads.
// ---------------------------------------------------------------------------
__global__ __launch_bounds__(256) void wino_gemm_tc() {
    const int ab = blockIdx.y;
    const int b0 = blockIdx.x * 128;

    __shared__ float Ws[64][64];    // [i][o], swizzled   (A accessed as A[m][k]=Ws[k][m])
    __shared__ float Vs[64][128];   // [i][t], swizzled   (B operand)

    const int tid = threadIdx.x;

    // load weights (coalesced float4, swizzled store)
    {
        const float4* src = reinterpret_cast<const float4*>(g_Wt + (size_t)ab * CC * CC);
#pragma unroll
        for (int idx = tid; idx < 1024; idx += 256) {
            int i  = idx >> 4;            // row (k)
            int o4 = idx & 15;            // col in float4 units
            int o4s = o4 ^ ((i & 3) << 1);
            *reinterpret_cast<float4*>(&Ws[i][o4s * 4]) = src[idx];
        }
    }
    // load V slab (coalesced float4, swizzled store)
    {
#pragma unroll
        for (int idx = tid; idx < 2048; idx += 256) {
            int i  = idx >> 5;            // row (k)
            int t4 = idx & 31;
            int t4s = t4 ^ ((i & 3) << 1);
            *reinterpret_cast<float4*>(&Vs[i][t4s * 4]) =
                *reinterpret_cast<const float4*>(g_V + ((size_t)ab * CC + i) * BB + b0 + t4 * 4);
        }
    }
    __syncthreads();

    const int lane = tid & 31;
    const int warp = tid >> 5;
    const int m_base = (warp & 3) * 16;   // 4 m-groups
    const int n_base = (warp >> 2) * 64;  // 2 n-groups
    const int g  = lane >> 2;             // 0..7
    const int tg = lane & 3;              // 0..3

    float acc[8][4];
#pragma unroll
    for (int n = 0; n < 8; n++)
#pragma unroll
        for (int c = 0; c < 4; c++) acc[n][c] = 0.f;

#pragma unroll
    for (int k0 = 0; k0 < 8; k0++) {
        const int kr = k0 * 8 + tg;           // A/B fragment rows (k dim)
        const int sw = tg << 3;               // (kr&3)<<3 == tg<<3 (also for kr+4)

        // A fragments: A[m][k] = Ws[k][m]
        uint32_t a0 = __float_as_uint(Ws[kr    ][(m_base + g)     ^ sw]);
        uint32_t a1 = __float_as_uint(Ws[kr    ][(m_base + g + 8) ^ sw]);
        uint32_t a2 = __float_as_uint(Ws[kr + 4][(m_base + g)     ^ sw]);
        uint32_t a3 = __float_as_uint(Ws[kr + 4][(m_base + g + 8) ^ sw]);

#pragma unroll
        for (int n = 0; n < 8; n++) {
            const int nn = n_base + n * 8;
            uint32_t b0r = __float_as_uint(Vs[kr    ][(nn + g) ^ sw]);
            uint32_t b1r = __float_as_uint(Vs[kr + 4][(nn + g) ^ sw]);
            asm volatile(
                "mma.sync.aligned.m16n8k8.row.col.f32.tf32.tf32.f32 "
                "{%0,%1,%2,%3}, {%4,%5,%6,%7}, {%8,%9}, {%0,%1,%2,%3};\n"
                : "+f"(acc[n][0]), "+f"(acc[n][1]), "+f"(acc[n][2]), "+f"(acc[n][3])
                : "r"(a0), "r"(a1), "r"(a2), "r"(a3), "r"(b0r), "r"(b1r));
        }
    }

    // store: c0/c1 -> (m_base+g, nn+2tg..+1), c2/c3 -> (m_base+g+8, ...)
#pragma unroll
    for (int n = 0; n < 8; n++) {
        const int col = b0 + n_base + n * 8 + 2 * tg;
        float* mp0 = g_M + ((size_t)ab * CC + (m_base + g)) * BB + col;
        float* mp1 = g_M + ((size_t)ab * CC + (m_base + g + 8)) * BB + col;
        *reinterpret_cast<float2*>(mp0) = make_float2(acc[n][0], acc[n][1]);
        *reinterpret_cast<float2*>(mp1) = make_float2(acc[n][2], acc[n][3]);
    }
}

// ---------------------------------------------------------------------------
// Kernel 3: output transform Y = AT * M * AT^T + bias, write to y
// grid = (BB/256, 64 o), block = 256 (one tile position per thread)
// ---------------------------------------------------------------------------
__global__ __launch_bounds__(256) void wino_out(float* __restrict__ y,
                                                const float* __restrict__ bias) {
    const int o = blockIdx.y;
    const int Bidx = blockIdx.x * 256 + threadIdx.x;

    float m[36];
#pragma unroll
    for (int ab = 0; ab < 36; ab++)
        m[ab] = g_M[((size_t)ab * CC + o) * BB + Bidx];

    // rows: t[x][b] = AT_x . m[:,b]
    float t[4][6];
#pragma unroll
    for (int b = 0; b < 6; b++) {
        float m0 = m[b], m1 = m[6 + b], m2 = m[12 + b];
        float m3 = m[18 + b], m4 = m[24 + b], m5 = m[30 + b];
        t[0][b] = m0 + m1 + m2 + m3 + m4;
        t[1][b] = m1 - m2 + 2.f * m3 - 2.f * m4;
        t[2][b] = m1 + m2 + 4.f * m3 + 4.f * m4;
        t[3][b] = m1 - m2 + 8.f * m3 - 8.f * m4 + m5;
    }

    const float bv = bias[o];
    const int n = Bidx >> 10;
    const int rem = Bidx & 1023;
    const int p = rem >> 5;
    const int q = rem & 31;
    float* yp = y + (((size_t)(n * CC + o)) * HH + 4 * p) * HH + 4 * q;

#pragma unroll
    for (int x = 0; x < 4; x++) {
        float m0 = t[x][0], m1 = t[x][1], m2 = t[x][2];
        float m3 = t[x][3], m4 = t[x][4], m5 = t[x][5];
        float4 r;
        r.x = m0 + m1 + m2 + m3 + m4 + bv;
        r.y = m1 - m2 + 2.f * m3 - 2.f * m4 + bv;
        r.z = m1 + m2 + 4.f * m3 + 4.f * m4 + bv;
        r.w = m1 - m2 + 8.f * m3 - 8.f * m4 + m5 + bv;
        *reinterpret_cast<float4*>(yp + x * HH) = r;
    }
}

// ---------------------------------------------------------------------------
extern "C" void kernel_launch(void* const* d_in, const int* in_sizes, int n_in,
                              void* d_out, int out_size) {
    const float* x    = (const float*)d_in[0];
    const float* w    = (const float*)d_in[1];
    const float* bias = (const float*)d_in[2];
    float* y = (float*)d_out;

    wino_wt<<<(AB * CC * CC + 255) / 256, 256>>>(w);
    wino_in<<<NN * NT, dim3(32, 8)>>>(x);
    wino_gemm_tc<<<dim3(BB / 128, AB), 256>>>();
    wino_out<<<dim3(BB / 256, CC), 256>>>(y, bias);
}